// round 5
// baseline (speedup 1.0000x reference)
#include <cuda_runtime.h>
#include <cstdint>

#define SLATE   5
#define DDIM    20
#define KSEL    100
#define NBINS   2048
#define CAP     131072
#define SMAX    131072
#define SH_CAND 12288
#define SV_CAP  512
#define STGT    128        // sample-count guarantee target (>= KSEL)

// -------- device scratch (allocation-free module globals) --------
__device__ float              g_proto[128];
__device__ float              g_pn2[8];
__device__ unsigned           g_hist[SLATE * NBINS];
__device__ unsigned           g_skey[(size_t)SLATE * SMAX];   // sample keys, 2.5 MB
__device__ unsigned           g_thresh[8];                    // exclusive 32-bit key limit
__device__ unsigned           g_candCount[8];
__device__ unsigned long long g_cand[(size_t)SLATE * CAP];    // 5 MB
__device__ unsigned           g_dummy;

__device__ __forceinline__ float leaky(float x) { return x > 0.0f ? x : 0.01f * x; }

// ---- packed f32x2 helpers (Blackwell FFMA2 via PTX) ----
__device__ __forceinline__ unsigned long long pk2(float lo, float hi) {
    unsigned long long r;
    asm("mov.b64 %0, {%1, %2};" : "=l"(r) : "f"(lo), "f"(hi));
    return r;
}
__device__ __forceinline__ void upk2(unsigned long long v, float& lo, float& hi) {
    asm("mov.b64 {%0, %1}, %2;" : "=f"(lo), "=f"(hi) : "l"(v));
}
__device__ __forceinline__ unsigned long long fma2(
    unsigned long long a, unsigned long long b, unsigned long long c) {
    unsigned long long d;
    asm("fma.rn.f32x2 %0, %1, %2, %3;" : "=l"(d) : "l"(a), "l"(b), "l"(c));
    return d;
}

// ---- scalar math: sample uses these; packed path is per-lane identical ----
__device__ __forceinline__ void unpack20(const float4* d5, float* vv) {
    #pragma unroll
    for (int q = 0; q < 5; q++) {
        float4 v = d5[q];
        vv[4*q+0] = v.x; vv[4*q+1] = v.y; vv[4*q+2] = v.z; vv[4*q+3] = v.w;
    }
}
__device__ __forceinline__ float norm20(const float* vv) {
    float c = 0.0f;
    #pragma unroll
    for (int k = 0; k < DDIM; k++) c = fmaf(vv[k], vv[k], c);
    return c;
}
__device__ __forceinline__ float dot20s(const float* p, const float* vv) {
    float d = 0.0f;
    #pragma unroll
    for (int k = 0; k < DDIM; k++) d = fmaf(p[k], vv[k], d);
    return d;
}
__device__ __forceinline__ unsigned key20(float cn2, float dot, float pn) {
    float d2 = fmaf(-2.0f, dot, cn2) + pn;
    d2 = fmaxf(d2, 0.0f);               // positive floats: raw bits monotone
    return __float_as_uint(d2);
}

// ---- block-wide "first bin with inclusive cum >= r" over NB bins ----
template<int NB, int BD>
__device__ void find_bin(const unsigned* hist, unsigned r, unsigned* warpsum,
                         unsigned* s_res, unsigned* s_prefix)
{
    const int tid = threadIdx.x;
    constexpr int PB = NB / BD;
    unsigned local[PB];
    unsigned v = 0;
    #pragma unroll
    for (int p = 0; p < PB; p++) { local[p] = hist[tid * PB + p]; v += local[p]; }

    unsigned inc = v;
    #pragma unroll
    for (int d = 1; d < 32; d <<= 1) {
        unsigned t = __shfl_up_sync(0xFFFFFFFFu, inc, d);
        if ((tid & 31) >= d) inc += t;
    }
    if ((tid & 31) == 31) warpsum[tid >> 5] = inc;
    if (tid == 0) *s_res = 0xFFFFFFFFu;
    __syncthreads();

    if (tid < 32) {
        constexpr int NW = BD / 32;
        unsigned w = (tid < NW) ? warpsum[tid] : 0u;
        #pragma unroll
        for (int d = 1; d < 32; d <<= 1) {
            unsigned t = __shfl_up_sync(0xFFFFFFFFu, w, d);
            if (tid >= d) w += t;
        }
        warpsum[tid] = w;
    }
    __syncthreads();

    unsigned base   = (tid >= 32) ? warpsum[(tid >> 5) - 1] : 0u;
    unsigned before = base + inc - v;
    unsigned run = before;
    unsigned myBin = 0xFFFFFFFFu;
    #pragma unroll
    for (int p = 0; p < PB; p++) {
        run += local[p];
        if (myBin == 0xFFFFFFFFu && run >= r) myBin = (unsigned)(tid * PB + p);
    }
    if (myBin != 0xFFFFFFFFu) atomicMin(s_res, myBin);
    __syncthreads();

    unsigned winner = *s_res;
    if (winner != 0xFFFFFFFFu && winner / PB == (unsigned)tid) {
        unsigned pf = before;
        for (unsigned p = 0; p < winner % PB; p++) pf += local[p];
        *s_prefix = pf;
    }
    __syncthreads();
}

// -------- kernel 1: MLP + zero scratch --------
__global__ __launch_bounds__(1024) void mlp_kernel(
    const float* __restrict__ x_in,
    const float* __restrict__ W0, const float* __restrict__ b0,
    const float* __restrict__ W1, const float* __restrict__ b1,
    const float* __restrict__ W2, const float* __restrict__ b2)
{
    __shared__ float x[DDIM];
    __shared__ float h0[256];
    __shared__ float h1[512];
    __shared__ float p2[2 * 512];
    __shared__ float p3[8 * 100];
    __shared__ float pr[100];
    int tid = threadIdx.x;

    for (int i = tid; i < SLATE * NBINS; i += 1024) g_hist[i] = 0;
    if (tid < 8) g_candCount[tid] = 0;

    if (tid < DDIM) x[tid] = x_in[tid];
    __syncthreads();

    if (tid < 256) {
        float acc = b0[tid];
        #pragma unroll
        for (int k = 0; k < DDIM; k++) acc = fmaf(x[k], W0[k * 256 + tid], acc);
        h0[tid] = leaky(acc);
    }
    __syncthreads();

    {   // layer 2: 512 outputs, k split 2 ways
        int o = tid & 511, c = tid >> 9;
        float acc = 0.0f;
        int k0 = c * 128;
        #pragma unroll 8
        for (int k = k0; k < k0 + 128; k++) acc = fmaf(h0[k], W1[k * 512 + o], acc);
        p2[c * 512 + o] = acc;
    }
    __syncthreads();
    if (tid < 512) h1[tid] = leaky(b1[tid] + p2[tid] + p2[512 + tid]);
    __syncthreads();

    {   // layer 3: 100 outputs, k split 8 ways
        int o = tid & 127, c = tid >> 7;
        if (o < 100) {
            float acc = 0.0f;
            int k0 = c * 64;
            #pragma unroll 8
            for (int k = k0; k < k0 + 64; k++) acc = fmaf(h1[k], W2[k * 100 + o], acc);
            p3[c * 100 + o] = acc;
        }
    }
    __syncthreads();
    if (tid < 100) {
        float s = b2[tid];
        #pragma unroll
        for (int c = 0; c < 8; c++) s += p3[c * 100 + tid];  // fixed order
        float v = leaky(s);
        pr[tid] = v;
        g_proto[tid] = v;
    }
    __syncthreads();
    if (tid < SLATE) {
        float s = 0.0f;
        #pragma unroll
        for (int d = 0; d < DDIM; d++) { float v = pr[tid * DDIM + d]; s = fmaf(v, v, s); }
        g_pn2[tid] = s;
    }
}

// -------- kernel 2: sample keys + coarse histogram --------
// Samples contiguous 256-doc chunks (1/16 of data). Keys stored for refine.
__global__ __launch_bounds__(512) void sample_kernel(const float* __restrict__ docs,
                                                     int N, int S)
{
    __shared__ unsigned shist[SLATE * NBINS];   // 40 KB
    __shared__ float    sp[100];
    __shared__ float    spn[SLATE];
    int tid = threadIdx.x;

    for (int t = tid; t < SLATE * NBINS; t += 512) shist[t] = 0;
    if (tid < 100) sp[tid] = g_proto[tid];
    if (tid < SLATE) spn[tid] = g_pn2[tid];
    __syncthreads();

    const float4* d4 = (const float4*)docs;
    for (int s = blockIdx.x * blockDim.x + tid; s < S; s += gridDim.x * blockDim.x) {
        int i = ((s >> 8) << 12) + (s & 255);     // chunk c -> docs [4096c, 4096c+256)
        if (i >= N) continue;
        float4 dv[5];
        size_t base = (size_t)i * 5;
        #pragma unroll
        for (int q = 0; q < 5; q++) dv[q] = d4[base + q];
        float vv[20];
        unpack20(dv, vv);
        float cn2 = norm20(vv);
        #pragma unroll
        for (int j = 0; j < SLATE; j++) {
            float dot = dot20s(&sp[j * DDIM], vv);
            unsigned key = key20(cn2, dot, spn[j]);
            g_skey[(size_t)j * SMAX + s] = key;
            unsigned hidx = j * NBINS + (key >> 21);
            unsigned am = __activemask();
            unsigned m  = __match_any_sync(am, hidx);
            if ((int)(threadIdx.x & 31) == (__ffs(m) - 1))
                atomicAdd(&shist[hidx], (unsigned)__popc(m));
        }
    }
    __syncthreads();
    for (int t = tid; t < SLATE * NBINS; t += 512) {
        unsigned c = shist[t];
        if (c) atomicAdd(&g_hist[t], c);
    }
}

// -------- kernel 3: refine threshold to 2^10 key granularity --------
__global__ __launch_bounds__(1024) void refine_kernel(int S)
{
    __shared__ unsigned hist[NBINS];
    __shared__ unsigned swarp[32];
    __shared__ unsigned sres, spre;
    int j = blockIdx.x, tid = threadIdx.x;

    for (int i = tid; i < NBINS; i += 1024) hist[i] = g_hist[j * NBINS + i];
    __syncthreads();
    find_bin<NBINS, 1024>(hist, STGT, swarp, &sres, &spre);
    unsigned bA = sres, pfA = spre;
    __syncthreads();
    if (bA == 0xFFFFFFFFu) { if (tid == 0) g_thresh[j] = 0xFFFFFFFFu; return; }
    unsigned rB = STGT - pfA;

    for (int i = tid; i < NBINS; i += 1024) hist[i] = 0;
    __syncthreads();
    for (int s = tid; s < S; s += 1024) {
        unsigned k = g_skey[(size_t)j * SMAX + s];
        if ((k >> 21) == bA) atomicAdd(&hist[(k >> 10) & 0x7FFu], 1u);
    }
    __syncthreads();
    find_bin<NBINS, 1024>(hist, rB, swarp, &sres, &spre);
    if (tid == 0) {
        unsigned long long T =
            ((((unsigned long long)bA << 11) | sres) + 1ull) << 10;
        g_thresh[j] = (T > 0xFFFFFFFFull) ? 0xFFFFFFFFu : (unsigned)T;
    }
}

// -------- kernel 4: fused score + collect, 2 docs/thread, packed f32x2 ----
__global__ __launch_bounds__(512) void score_kernel(const float* __restrict__ docs, int N)
{
    __shared__ unsigned long long spd[SLATE * DDIM];   // dup-packed proto
    __shared__ float    spn[SLATE];
    __shared__ unsigned sT[SLATE];
    int tid = threadIdx.x;

    if (tid < 100) { float p = g_proto[tid]; spd[tid] = pk2(p, p); }
    if (tid < SLATE) { spn[tid] = g_pn2[tid]; sT[tid] = g_thresh[tid]; }
    __syncthreads();

    const int lane = threadIdx.x & 31;
    const float4* d4 = (const float4*)docs;
    int stride2 = gridDim.x * blockDim.x * 2;

    for (int i0 = (blockIdx.x * blockDim.x + tid) * 2; i0 < N; i0 += stride2) {
        bool two = (i0 + 1 < N);
        float4 da[5], db[5];
        size_t ba = (size_t)i0 * 5;
        size_t bb = two ? ba + 5 : ba;
        #pragma unroll
        for (int q = 0; q < 5; q++) { da[q] = d4[ba + q]; db[q] = d4[bb + q]; }
        float va[20], vb[20];
        unpack20(da, va);
        unpack20(db, vb);

        unsigned long long v2[20];
        #pragma unroll
        for (int k = 0; k < DDIM; k++) v2[k] = pk2(va[k], vb[k]);

        unsigned long long n2 = 0ull;   // (0.0f, 0.0f)
        #pragma unroll
        for (int k = 0; k < DDIM; k++) n2 = fma2(v2[k], v2[k], n2);
        float cnA, cnB;
        upk2(n2, cnA, cnB);

        #pragma unroll
        for (int j = 0; j < SLATE; j++) {
            unsigned long long acc = 0ull;
            #pragma unroll
            for (int k = 0; k < DDIM; k++) acc = fma2(v2[k], spd[j * DDIM + k], acc);
            float dA, dB;
            upk2(acc, dA, dB);
            unsigned keyA = key20(cnA, dA, spn[j]);
            unsigned keyB = key20(cnB, dB, spn[j]);
            bool hA = keyA < sT[j];
            bool hB = two && (keyB < sT[j]);

            unsigned am = __activemask();
            unsigned mA = __ballot_sync(am, hA);
            unsigned mB = __ballot_sync(am, hB);
            unsigned tot = (unsigned)__popc(mA) + (unsigned)__popc(mB);
            if (tot) {
                unsigned ldr = (unsigned)(__ffs(am) - 1);
                unsigned bpos = 0;
                if ((unsigned)lane == ldr) bpos = atomicAdd(&g_candCount[j], tot);
                bpos = __shfl_sync(am, bpos, ldr);
                unsigned below = (1u << lane) - 1u;
                if (hA) {
                    unsigned pos = bpos + (unsigned)__popc(mA & below);
                    if (pos < CAP)
                        g_cand[(size_t)j * CAP + pos] =
                            ((unsigned long long)keyA << 32) | (unsigned)i0;
                }
                if (hB) {
                    unsigned pos = bpos + (unsigned)__popc(mA)
                                 + (unsigned)__popc(mB & below);
                    if (pos < CAP)
                        g_cand[(size_t)j * CAP + pos] =
                            ((unsigned long long)keyB << 32) | (unsigned)(i0 + 1);
                }
            }
        }
    }
}

// -------- kernel 5: radix select of exact 100th + rank survivors + gather ----
__global__ __launch_bounds__(1024) void select_kernel(
    const float* __restrict__ docs, float* __restrict__ out, int out_size)
{
    extern __shared__ unsigned long long sc[];      // SH_CAND packed candidates
    __shared__ unsigned           hist[NBINS];
    __shared__ unsigned           swarp[32];
    __shared__ unsigned           sres, spre;
    __shared__ unsigned long long sv[SV_CAP];
    __shared__ unsigned           svCount;

    int j   = blockIdx.x;
    int tid = threadIdx.x;
    size_t cbase = (size_t)j * CAP;
    int n = (int)min(g_candCount[j], (unsigned)CAP);
    int nsh = n < SH_CAND ? n : SH_CAND;

    if (tid == 0) svCount = 0;
    for (int t = tid; t < nsh; t += 1024) sc[t] = g_cand[cbase + t];
    __syncthreads();

    // pass A: bits 31..21
    for (int i = tid; i < NBINS; i += 1024) hist[i] = 0;
    __syncthreads();
    for (int t = tid; t < n; t += 1024) {
        unsigned k = (unsigned)(((t < nsh) ? sc[t] : g_cand[cbase + t]) >> 32);
        unsigned b = k >> 21;
        unsigned am = __activemask();
        unsigned m  = __match_any_sync(am, b);
        if ((int)(tid & 31) == (__ffs(m) - 1)) atomicAdd(&hist[b], (unsigned)__popc(m));
    }
    __syncthreads();
    find_bin<NBINS, 1024>(hist, KSEL, swarp, &sres, &spre);
    unsigned bA = sres;
    unsigned rB = KSEL - spre;
    __syncthreads();

    // pass B: bits 20..10 within bA
    for (int i = tid; i < NBINS; i += 1024) hist[i] = 0;
    __syncthreads();
    for (int t = tid; t < n; t += 1024) {
        unsigned k = (unsigned)(((t < nsh) ? sc[t] : g_cand[cbase + t]) >> 32);
        if ((k >> 21) == bA) atomicAdd(&hist[(k >> 10) & 0x7FFu], 1u);
    }
    __syncthreads();
    find_bin<NBINS, 1024>(hist, rB, swarp, &sres, &spre);
    unsigned bB = sres;
    unsigned rC = rB - spre;
    unsigned hi21 = (bA << 11) | bB;
    __syncthreads();

    // pass C: bits 9..0 within (bA,bB)
    if (tid < 1024) hist[tid] = 0;
    __syncthreads();
    for (int t = tid; t < n; t += 1024) {
        unsigned k = (unsigned)(((t < nsh) ? sc[t] : g_cand[cbase + t]) >> 32);
        if ((k >> 10) == hi21) atomicAdd(&hist[k & 0x3FFu], 1u);
    }
    __syncthreads();
    find_bin<1024, 1024>(hist, rC, swarp, &sres, &spre);
    unsigned Kstar = (hi21 << 10) | sres;
    __syncthreads();

    // survivors: key <= Kstar (ties resolved by packed 64-bit rank)
    for (int t = tid; t < n; t += 1024) {
        unsigned long long pk = (t < nsh) ? sc[t] : g_cand[cbase + t];
        if ((unsigned)(pk >> 32) <= Kstar) {
            unsigned pos = atomicAdd(&svCount, 1u);
            if (pos < SV_CAP) sv[pos] = pk;
        }
    }
    __syncthreads();

    int S = (int)min(svCount, (unsigned)SV_CAP);
    for (int t = tid; t < S; t += 1024) {
        unsigned long long my = sv[t];
        int rank = 0;
        for (int s = 0; s < S; s++) rank += (sv[s] < my);
        if (rank < KSEL) {
            unsigned di = (unsigned)(my & 0xFFFFFFFFu);
            int orow = j * KSEL + rank;
            if (out_size >= SLATE * KSEL * DDIM) {
                const float4* s4 = (const float4*)(docs + (size_t)di * DDIM);
                float4* o4 = (float4*)(out + (size_t)orow * DDIM);
                #pragma unroll
                for (int q = 0; q < 5; q++) o4[q] = s4[q];
                if (out_size >= SLATE * KSEL * DDIM + SLATE * KSEL)
                    out[SLATE * KSEL * DDIM + orow] = (float)di;
            } else {
                out[orow] = (float)di;
            }
        }
    }
}

extern "C" void kernel_launch(void* const* d_in, const int* in_sizes, int n_in,
                              void* d_out, int out_size)
{
    const float* state = (const float*)d_in[0];
    const float* docs  = (const float*)d_in[1];
    const float* W0    = (const float*)d_in[2];
    const float* b0    = (const float*)d_in[3];
    const float* W1    = (const float*)d_in[4];
    const float* b1    = (const float*)d_in[5];
    const float* W2    = (const float*)d_in[6];
    const float* b2    = (const float*)d_in[7];
    float* out = (float*)d_out;

    int N = in_sizes[1] / DDIM;
    int S = N >> 4;               // 1/16 sample
    if (S < 1) S = N;
    if (S > SMAX) S = SMAX;

    const int threads = 512;
    int blocks = (N + threads * 4 - 1) / (threads * 4);
    if (blocks > 2048) blocks = 2048;
    if (blocks < 1) blocks = 1;

    cudaFuncSetAttribute(select_kernel,
        cudaFuncAttributeMaxDynamicSharedMemorySize, SH_CAND * sizeof(unsigned long long));

    mlp_kernel<<<1, 1024>>>(state, W0, b0, W1, b1, W2, b2);
    sample_kernel<<<128, 512>>>(docs, N, S);
    refine_kernel<<<SLATE, 1024>>>(S);
    score_kernel<<<blocks, threads>>>(docs, N);
    select_kernel<<<SLATE, 1024, SH_CAND * sizeof(unsigned long long)>>>(docs, out, out_size);
}

// round 6
// speedup vs baseline: 1.1102x; 1.1102x over previous
#include <cuda_runtime.h>
#include <cstdint>

#define SLATE   5
#define DDIM    20
#define KSEL    100
#define NBINS   2048
#define CAP     131072
#define SMAX    131072
#define SH_CAND 12288
#define SV_CAP  512
#define STGT    128        // sample-count guarantee target (>= KSEL)
#define TILE    1024       // docs per score tile (80 KB smem)

// -------- device scratch (allocation-free module globals) --------
__device__ float              g_proto[128];
__device__ float              g_pn2[8];
__device__ unsigned           g_hist[SLATE * NBINS];
__device__ unsigned           g_skey[(size_t)SLATE * SMAX];   // sample keys
__device__ unsigned           g_thresh[8];                    // exclusive key limit
__device__ unsigned           g_candCount[8];
__device__ unsigned long long g_cand[(size_t)SLATE * CAP];

__device__ __forceinline__ float leaky(float x) { return x > 0.0f ? x : 0.01f * x; }

// ---- packed f32x2 helpers (Blackwell FFMA2 via PTX) ----
__device__ __forceinline__ unsigned long long pk2(float lo, float hi) {
    unsigned long long r;
    asm("mov.b64 %0, {%1, %2};" : "=l"(r) : "f"(lo), "f"(hi));
    return r;
}
__device__ __forceinline__ void upk2(unsigned long long v, float& lo, float& hi) {
    asm("mov.b64 {%0, %1}, %2;" : "=f"(lo), "=f"(hi) : "l"(v));
}
__device__ __forceinline__ unsigned long long fma2(
    unsigned long long a, unsigned long long b, unsigned long long c) {
    unsigned long long d;
    asm("fma.rn.f32x2 %0, %1, %2, %3;" : "=l"(d) : "l"(a), "l"(b), "l"(c));
    return d;
}

// ---- scalar math (sample path; packed path is per-lane IEEE-identical) ----
__device__ __forceinline__ void unpack20(const float4* d5, float* vv) {
    #pragma unroll
    for (int q = 0; q < 5; q++) {
        float4 v = d5[q];
        vv[4*q+0] = v.x; vv[4*q+1] = v.y; vv[4*q+2] = v.z; vv[4*q+3] = v.w;
    }
}
__device__ __forceinline__ float norm20(const float* vv) {
    float c = 0.0f;
    #pragma unroll
    for (int k = 0; k < DDIM; k++) c = fmaf(vv[k], vv[k], c);
    return c;
}
__device__ __forceinline__ float dot20s(const float* p, const float* vv) {
    float d = 0.0f;
    #pragma unroll
    for (int k = 0; k < DDIM; k++) d = fmaf(p[k], vv[k], d);
    return d;
}
__device__ __forceinline__ unsigned key20(float cn2, float dot, float pn) {
    float d2 = fmaf(-2.0f, dot, cn2) + pn;
    d2 = fmaxf(d2, 0.0f);               // positive floats: raw bits monotone
    return __float_as_uint(d2);
}

// ---- block-wide "first bin with inclusive cum >= r" over NB bins ----
template<int NB, int BD>
__device__ void find_bin(const unsigned* hist, unsigned r, unsigned* warpsum,
                         unsigned* s_res, unsigned* s_prefix)
{
    const int tid = threadIdx.x;
    constexpr int PB = NB / BD;
    unsigned local[PB];
    unsigned v = 0;
    #pragma unroll
    for (int p = 0; p < PB; p++) { local[p] = hist[tid * PB + p]; v += local[p]; }

    unsigned inc = v;
    #pragma unroll
    for (int d = 1; d < 32; d <<= 1) {
        unsigned t = __shfl_up_sync(0xFFFFFFFFu, inc, d);
        if ((tid & 31) >= d) inc += t;
    }
    if ((tid & 31) == 31) warpsum[tid >> 5] = inc;
    if (tid == 0) *s_res = 0xFFFFFFFFu;
    __syncthreads();

    if (tid < 32) {
        constexpr int NW = BD / 32;
        unsigned w = (tid < NW) ? warpsum[tid] : 0u;
        #pragma unroll
        for (int d = 1; d < 32; d <<= 1) {
            unsigned t = __shfl_up_sync(0xFFFFFFFFu, w, d);
            if (tid >= d) w += t;
        }
        warpsum[tid] = w;
    }
    __syncthreads();

    unsigned base   = (tid >= 32) ? warpsum[(tid >> 5) - 1] : 0u;
    unsigned before = base + inc - v;
    unsigned run = before;
    unsigned myBin = 0xFFFFFFFFu;
    #pragma unroll
    for (int p = 0; p < PB; p++) {
        run += local[p];
        if (myBin == 0xFFFFFFFFu && run >= r) myBin = (unsigned)(tid * PB + p);
    }
    if (myBin != 0xFFFFFFFFu) atomicMin(s_res, myBin);
    __syncthreads();

    unsigned winner = *s_res;
    if (winner != 0xFFFFFFFFu && winner / PB == (unsigned)tid) {
        unsigned pf = before;
        for (unsigned p = 0; p < winner % PB; p++) pf += local[p];
        *s_prefix = pf;
    }
    __syncthreads();
}

// -------- kernel 1: MLP (o-vectorized float4 GEMVs) + zero scratch --------
__global__ __launch_bounds__(1024) void mlp_kernel(
    const float* __restrict__ x_in,
    const float* __restrict__ W0, const float* __restrict__ b0,
    const float* __restrict__ W1, const float* __restrict__ b1,
    const float* __restrict__ W2, const float* __restrict__ b2)
{
    __shared__ float x[DDIM];
    __shared__ float h0[256];
    __shared__ float h1[512];
    __shared__ float p2[8 * 512];     // 16 KB
    __shared__ float p3[32 * 100];    // 12.8 KB
    __shared__ float pr[100];
    int tid = threadIdx.x;

    for (int i = tid; i < SLATE * NBINS; i += 1024) g_hist[i] = 0;
    if (tid < 8) g_candCount[tid] = 0;

    if (tid < DDIM) x[tid] = x_in[tid];
    __syncthreads();

    if (tid < 256) {
        float acc = b0[tid];
        #pragma unroll
        for (int k = 0; k < DDIM; k++) acc = fmaf(x[k], W0[k * 256 + tid], acc);
        h0[tid] = leaky(acc);
    }
    __syncthreads();

    {   // layer 2: 512 outputs; float4 along o (coalesced), k split 8 ways
        int o4 = (tid & 127);         // float4 index: outputs 4*o4..4*o4+3
        int c  = tid >> 7;            // 0..7, k-chunk of 32
        const float4* W1v = (const float4*)W1;
        float4 acc = make_float4(0.f, 0.f, 0.f, 0.f);
        int k0 = c * 32;
        #pragma unroll 8
        for (int k = k0; k < k0 + 32; k++) {
            float h = h0[k];
            float4 w = W1v[k * 128 + o4];
            acc.x = fmaf(h, w.x, acc.x); acc.y = fmaf(h, w.y, acc.y);
            acc.z = fmaf(h, w.z, acc.z); acc.w = fmaf(h, w.w, acc.w);
        }
        ((float4*)(p2 + c * 512))[o4] = acc;
    }
    __syncthreads();
    if (tid < 512) {
        float s = b1[tid];
        #pragma unroll
        for (int c = 0; c < 8; c++) s += p2[c * 512 + tid];  // fixed order
        h1[tid] = leaky(s);
    }
    __syncthreads();

    {   // layer 3: 100 outputs; float4 along o (25 float4s), k split 32 ways
        int t = tid & 31;             // float4 index 0..24 active
        int c = tid >> 5;             // 0..31, k-chunk of 16
        if (t < 25) {
            const float4* W2v = (const float4*)W2;   // row = 25 float4s (400 B)
            float4 acc = make_float4(0.f, 0.f, 0.f, 0.f);
            int k0 = c * 16;
            #pragma unroll 8
            for (int k = k0; k < k0 + 16; k++) {
                float h = h1[k];
                float4 w = W2v[k * 25 + t];
                acc.x = fmaf(h, w.x, acc.x); acc.y = fmaf(h, w.y, acc.y);
                acc.z = fmaf(h, w.z, acc.z); acc.w = fmaf(h, w.w, acc.w);
            }
            p3[c * 100 + 4 * t + 0] = acc.x;
            p3[c * 100 + 4 * t + 1] = acc.y;
            p3[c * 100 + 4 * t + 2] = acc.z;
            p3[c * 100 + 4 * t + 3] = acc.w;
        }
    }
    __syncthreads();
    if (tid < 100) {
        float s = b2[tid];
        #pragma unroll
        for (int c = 0; c < 32; c++) s += p3[c * 100 + tid]; // fixed order
        float v = leaky(s);
        pr[tid] = v;
        g_proto[tid] = v;
    }
    __syncthreads();
    if (tid < SLATE) {
        float s = 0.0f;
        #pragma unroll
        for (int d = 0; d < DDIM; d++) { float v = pr[tid * DDIM + d]; s = fmaf(v, v, s); }
        g_pn2[tid] = s;
    }
}

// -------- kernel 2: sample keys + coarse histogram --------
__global__ __launch_bounds__(512) void sample_kernel(const float* __restrict__ docs,
                                                     int N, int S)
{
    __shared__ unsigned shist[SLATE * NBINS];   // 40 KB
    __shared__ float    sp[100];
    __shared__ float    spn[SLATE];
    int tid = threadIdx.x;

    for (int t = tid; t < SLATE * NBINS; t += 512) shist[t] = 0;
    if (tid < 100) sp[tid] = g_proto[tid];
    if (tid < SLATE) spn[tid] = g_pn2[tid];
    __syncthreads();

    const float4* d4 = (const float4*)docs;
    for (int s = blockIdx.x * blockDim.x + tid; s < S; s += gridDim.x * blockDim.x) {
        int i = ((s >> 8) << 12) + (s & 255);     // chunk c -> docs [4096c, 4096c+256)
        if (i >= N) continue;
        float4 dv[5];
        size_t base = (size_t)i * 5;
        #pragma unroll
        for (int q = 0; q < 5; q++) dv[q] = d4[base + q];
        float vv[20];
        unpack20(dv, vv);
        float cn2 = norm20(vv);
        #pragma unroll
        for (int j = 0; j < SLATE; j++) {
            float dot = dot20s(&sp[j * DDIM], vv);
            unsigned key = key20(cn2, dot, spn[j]);
            g_skey[(size_t)j * SMAX + s] = key;
            unsigned hidx = j * NBINS + (key >> 21);
            unsigned am = __activemask();
            unsigned m  = __match_any_sync(am, hidx);
            if ((int)(threadIdx.x & 31) == (__ffs(m) - 1))
                atomicAdd(&shist[hidx], (unsigned)__popc(m));
        }
    }
    __syncthreads();
    for (int t = tid; t < SLATE * NBINS; t += 512) {
        unsigned c = shist[t];
        if (c) atomicAdd(&g_hist[t], c);
    }
}

// -------- kernel 3: refine threshold to 2^10 key granularity --------
__global__ __launch_bounds__(1024) void refine_kernel(int S)
{
    __shared__ unsigned hist[NBINS];
    __shared__ unsigned swarp[32];
    __shared__ unsigned sres, spre;
    int j = blockIdx.x, tid = threadIdx.x;

    for (int i = tid; i < NBINS; i += 1024) hist[i] = g_hist[j * NBINS + i];
    __syncthreads();
    find_bin<NBINS, 1024>(hist, STGT, swarp, &sres, &spre);
    unsigned bA = sres, pfA = spre;
    __syncthreads();
    if (bA == 0xFFFFFFFFu) { if (tid == 0) g_thresh[j] = 0xFFFFFFFFu; return; }
    unsigned rB = STGT - pfA;

    for (int i = tid; i < NBINS; i += 1024) hist[i] = 0;
    __syncthreads();
    for (int s = tid; s < S; s += 1024) {
        unsigned k = g_skey[(size_t)j * SMAX + s];
        if ((k >> 21) == bA) atomicAdd(&hist[(k >> 10) & 0x7FFu], 1u);
    }
    __syncthreads();
    find_bin<NBINS, 1024>(hist, rB, swarp, &sres, &spre);
    if (tid == 0) {
        unsigned long long T =
            ((((unsigned long long)bA << 11) | sres) + 1ull) << 10;
        g_thresh[j] = (T > 0xFFFFFFFFull) ? 0xFFFFFFFFu : (unsigned)T;
    }
}

// -------- kernel 4: fused score+collect, smem-staged tiles, f32x2 ----------
// Block stages TILE=1024 docs with fully coalesced LDG.128, then thread t
// computes docs (t, t+512) packed in f32x2. LDS.128 at 80 B stride with this
// pairing is bank-conflict-free. Accumulation chains per doc are k=0..19,
// bit-identical to the scalar sample path.
__global__ __launch_bounds__(512, 2) void score_kernel(const float* __restrict__ docs, int N)
{
    extern __shared__ float sd[];                      // TILE*20 floats (80 KB)
    __shared__ unsigned long long spd[SLATE * DDIM];   // dup-packed proto
    __shared__ float    spn[SLATE];
    __shared__ unsigned sT[SLATE];
    int tid = threadIdx.x;

    if (tid < 100) { float p = g_proto[tid]; spd[tid] = pk2(p, p); }
    if (tid < SLATE) { spn[tid] = g_pn2[tid]; sT[tid] = g_thresh[tid]; }

    const int lane = tid & 31;
    const float4* d4  = (const float4*)docs;
    float4*       sd4 = (float4*)sd;
    size_t nf4 = (size_t)N * 5;
    int nTiles = (N + TILE - 1) / TILE;

    for (int tile = blockIdx.x; tile < nTiles; tile += gridDim.x) {
        size_t fbase = (size_t)tile * (TILE * 5);
        __syncthreads();                              // protect sd reuse
        #pragma unroll
        for (int q = 0; q < 10; q++) {
            size_t g = fbase + tid + q * 512;
            if (g < nf4) sd4[tid + q * 512] = d4[g];
        }
        __syncthreads();

        int iA = tile * TILE + tid;
        int iB = iA + 512;
        bool okA = iA < N, okB = iB < N;

        const float4* sA = (const float4*)&sd[(size_t)tid * DDIM];
        const float4* sB = (const float4*)&sd[(size_t)(tid + 512) * DDIM];

        unsigned long long n2 = 0ull;
        unsigned long long acc0 = 0ull, acc1 = 0ull, acc2 = 0ull,
                           acc3 = 0ull, acc4 = 0ull;
        #pragma unroll
        for (int q = 0; q < 5; q++) {
            float4 fa = sA[q];
            float4 fb = sB[q];
            unsigned long long v0 = pk2(fa.x, fb.x);
            unsigned long long v1 = pk2(fa.y, fb.y);
            unsigned long long v2 = pk2(fa.z, fb.z);
            unsigned long long v3 = pk2(fa.w, fb.w);
            n2 = fma2(v0, v0, n2); n2 = fma2(v1, v1, n2);
            n2 = fma2(v2, v2, n2); n2 = fma2(v3, v3, n2);
            #pragma unroll
            for (int j = 0; j < SLATE; j++) {
                unsigned long long* aj =
                    (j == 0) ? &acc0 : (j == 1) ? &acc1 :
                    (j == 2) ? &acc2 : (j == 3) ? &acc3 : &acc4;
                *aj = fma2(v0, spd[j * DDIM + 4*q + 0], *aj);
                *aj = fma2(v1, spd[j * DDIM + 4*q + 1], *aj);
                *aj = fma2(v2, spd[j * DDIM + 4*q + 2], *aj);
                *aj = fma2(v3, spd[j * DDIM + 4*q + 3], *aj);
            }
        }
        float cnA, cnB;
        upk2(n2, cnA, cnB);

        #pragma unroll
        for (int j = 0; j < SLATE; j++) {
            unsigned long long acc =
                (j == 0) ? acc0 : (j == 1) ? acc1 :
                (j == 2) ? acc2 : (j == 3) ? acc3 : acc4;
            float dA, dB;
            upk2(acc, dA, dB);
            unsigned keyA = key20(cnA, dA, spn[j]);
            unsigned keyB = key20(cnB, dB, spn[j]);
            bool hA = okA && (keyA < sT[j]);
            bool hB = okB && (keyB < sT[j]);

            unsigned am = __activemask();
            unsigned mA = __ballot_sync(am, hA);
            unsigned mB = __ballot_sync(am, hB);
            unsigned tot = (unsigned)__popc(mA) + (unsigned)__popc(mB);
            if (tot) {
                unsigned ldr = (unsigned)(__ffs(am) - 1);
                unsigned bpos = 0;
                if ((unsigned)lane == ldr) bpos = atomicAdd(&g_candCount[j], tot);
                bpos = __shfl_sync(am, bpos, ldr);
                unsigned below = (1u << lane) - 1u;
                if (hA) {
                    unsigned pos = bpos + (unsigned)__popc(mA & below);
                    if (pos < CAP)
                        g_cand[(size_t)j * CAP + pos] =
                            ((unsigned long long)keyA << 32) | (unsigned)iA;
                }
                if (hB) {
                    unsigned pos = bpos + (unsigned)__popc(mA)
                                 + (unsigned)__popc(mB & below);
                    if (pos < CAP)
                        g_cand[(size_t)j * CAP + pos] =
                            ((unsigned long long)keyB << 32) | (unsigned)iB;
                }
            }
        }
    }
}

// -------- kernel 5: radix select of exact 100th + rank survivors + gather ----
__global__ __launch_bounds__(1024) void select_kernel(
    const float* __restrict__ docs, float* __restrict__ out, int out_size)
{
    extern __shared__ unsigned long long sc[];
    __shared__ unsigned           hist[NBINS];
    __shared__ unsigned           swarp[32];
    __shared__ unsigned           sres, spre;
    __shared__ unsigned long long sv[SV_CAP];
    __shared__ unsigned           svCount;

    int j   = blockIdx.x;
    int tid = threadIdx.x;
    size_t cbase = (size_t)j * CAP;
    int n = (int)min(g_candCount[j], (unsigned)CAP);
    int nsh = n < SH_CAND ? n : SH_CAND;

    if (tid == 0) svCount = 0;
    for (int t = tid; t < nsh; t += 1024) sc[t] = g_cand[cbase + t];
    __syncthreads();

    // pass A: bits 31..21
    for (int i = tid; i < NBINS; i += 1024) hist[i] = 0;
    __syncthreads();
    for (int t = tid; t < n; t += 1024) {
        unsigned k = (unsigned)(((t < nsh) ? sc[t] : g_cand[cbase + t]) >> 32);
        unsigned b = k >> 21;
        unsigned am = __activemask();
        unsigned m  = __match_any_sync(am, b);
        if ((int)(tid & 31) == (__ffs(m) - 1)) atomicAdd(&hist[b], (unsigned)__popc(m));
    }
    __syncthreads();
    find_bin<NBINS, 1024>(hist, KSEL, swarp, &sres, &spre);
    unsigned bA = sres;
    unsigned rB = KSEL - spre;
    __syncthreads();

    // pass B: bits 20..10 within bA
    for (int i = tid; i < NBINS; i += 1024) hist[i] = 0;
    __syncthreads();
    for (int t = tid; t < n; t += 1024) {
        unsigned k = (unsigned)(((t < nsh) ? sc[t] : g_cand[cbase + t]) >> 32);
        if ((k >> 21) == bA) atomicAdd(&hist[(k >> 10) & 0x7FFu], 1u);
    }
    __syncthreads();
    find_bin<NBINS, 1024>(hist, rB, swarp, &sres, &spre);
    unsigned bB = sres;
    unsigned rC = rB - spre;
    unsigned hi21 = (bA << 11) | bB;
    __syncthreads();

    // pass C: bits 9..0 within (bA,bB)
    if (tid < 1024) hist[tid] = 0;
    __syncthreads();
    for (int t = tid; t < n; t += 1024) {
        unsigned k = (unsigned)(((t < nsh) ? sc[t] : g_cand[cbase + t]) >> 32);
        if ((k >> 10) == hi21) atomicAdd(&hist[k & 0x3FFu], 1u);
    }
    __syncthreads();
    find_bin<1024, 1024>(hist, rC, swarp, &sres, &spre);
    unsigned Kstar = (hi21 << 10) | sres;
    __syncthreads();

    // survivors: key <= Kstar (ties resolved by packed 64-bit rank)
    for (int t = tid; t < n; t += 1024) {
        unsigned long long pk = (t < nsh) ? sc[t] : g_cand[cbase + t];
        if ((unsigned)(pk >> 32) <= Kstar) {
            unsigned pos = atomicAdd(&svCount, 1u);
            if (pos < SV_CAP) sv[pos] = pk;
        }
    }
    __syncthreads();

    int S = (int)min(svCount, (unsigned)SV_CAP);
    for (int t = tid; t < S; t += 1024) {
        unsigned long long my = sv[t];
        int rank = 0;
        for (int s = 0; s < S; s++) rank += (sv[s] < my);
        if (rank < KSEL) {
            unsigned di = (unsigned)(my & 0xFFFFFFFFu);
            int orow = j * KSEL + rank;
            if (out_size >= SLATE * KSEL * DDIM) {
                const float4* s4 = (const float4*)(docs + (size_t)di * DDIM);
                float4* o4 = (float4*)(out + (size_t)orow * DDIM);
                #pragma unroll
                for (int q = 0; q < 5; q++) o4[q] = s4[q];
                if (out_size >= SLATE * KSEL * DDIM + SLATE * KSEL)
                    out[SLATE * KSEL * DDIM + orow] = (float)di;
            } else {
                out[orow] = (float)di;
            }
        }
    }
}

extern "C" void kernel_launch(void* const* d_in, const int* in_sizes, int n_in,
                              void* d_out, int out_size)
{
    const float* state = (const float*)d_in[0];
    const float* docs  = (const float*)d_in[1];
    const float* W0    = (const float*)d_in[2];
    const float* b0    = (const float*)d_in[3];
    const float* W1    = (const float*)d_in[4];
    const float* b1    = (const float*)d_in[5];
    const float* W2    = (const float*)d_in[6];
    const float* b2    = (const float*)d_in[7];
    float* out = (float*)d_out;

    int N = in_sizes[1] / DDIM;
    int S = N >> 4;               // 1/16 sample
    if (S < 1) S = N;
    if (S > SMAX) S = SMAX;

    static int inited = 0;
    if (!inited) {
        cudaFuncSetAttribute(score_kernel,
            cudaFuncAttributeMaxDynamicSharedMemorySize, TILE * DDIM * sizeof(float));
        cudaFuncSetAttribute(select_kernel,
            cudaFuncAttributeMaxDynamicSharedMemorySize, SH_CAND * sizeof(unsigned long long));
        inited = 1;
    }

    int nTiles = (N + TILE - 1) / TILE;
    int sblocks = nTiles < 296 ? nTiles : 296;     // 2 blocks/SM residency
    if (sblocks < 1) sblocks = 1;

    mlp_kernel<<<1, 1024>>>(state, W0, b0, W1, b1, W2, b2);
    sample_kernel<<<128, 512>>>(docs, N, S);
    refine_kernel<<<SLATE, 1024>>>(S);
    score_kernel<<<sblocks, 512, TILE * DDIM * sizeof(float)>>>(docs, N);
    select_kernel<<<SLATE, 1024, SH_CAND * sizeof(unsigned long long)>>>(docs, out, out_size);
}